// round 1
// baseline (speedup 1.0000x reference)
#include <cuda_runtime.h>
#include <stdint.h>

// Problem constants
#define B_   4
#define H_   8
#define N_   2048
#define DV_  64
#define BH_  (B_ * H_)            // 32
#define COLS_ (BH_ * DV_)         // 2048 independent sort columns
#define OUT_ELEMS (BH_ * (size_t)N_ * DV_)   // 4,194,304 floats for 'out'
#define ATTN_ELEMS ((size_t)BH_ * N_ * N_)   // 134,217,728 floats for 'attn'

// ---------------- scratch (device globals; no allocations allowed) ----------
__device__ uint32_t g_key [COLS_ * N_];   // sortable-transformed v, [bh][d][i]  (16MB)
__device__ float    g_vs  [COLS_ * N_];   // sorted values,          [bh][d][r]  (16MB)
__device__ uint16_t g_inv [COLS_ * N_];   // rank of orig index i = inv(p_d)[i]  (8MB)
__device__ uint16_t g_p0  [BH_  * N_];    // p_0[r] (argsort of column d=0)      (128KB)
__device__ float    g_outt[COLS_ * N_];   // out in [bh][d][i] layout            (16MB)

// float <-> order-preserving uint32
__device__ __forceinline__ uint32_t f2sort(float x) {
    uint32_t u = __float_as_uint(x);
    return u ^ ((u & 0x80000000u) ? 0xFFFFFFFFu : 0x80000000u);
}
__device__ __forceinline__ float sort2f(uint32_t u) {
    u ^= (u & 0x80000000u) ? 0x80000000u : 0xFFFFFFFFu;
    return __uint_as_float(u);
}

// ---------------- 1) transpose v [bh][i][d] -> g_key [bh][d][i] (+transform) -
__global__ void k_transpose_in(const float* __restrict__ v) {
    __shared__ float tile[32][33];
    int bh = blockIdx.z;
    int i0 = blockIdx.x * 32;
    int d0 = blockIdx.y * 32;
    int tx = threadIdx.x, ty = threadIdx.y;     // block (32,8)
    const float* src = v + (size_t)bh * N_ * DV_;
#pragma unroll
    for (int r = 0; r < 32; r += 8)
        tile[ty + r][tx] = src[(size_t)(i0 + ty + r) * DV_ + (d0 + tx)];
    __syncthreads();
    uint32_t* dst = g_key + (size_t)bh * DV_ * N_;
#pragma unroll
    for (int r = 0; r < 32; r += 8)
        dst[(size_t)(d0 + ty + r) * N_ + (i0 + tx)] = f2sort(tile[tx][ty + r]);
}

// ---------------- 2) per-column bitonic sort of 2048 packed (key,idx) -------
// Stable argsort: packed (sortkey<<32 | idx) breaks ties by ascending idx.
__global__ __launch_bounds__(1024) void k_sort() {
    __shared__ uint64_t s[N_];
    const int col = blockIdx.x;            // bh*64 + d
    const int t = threadIdx.x;
    const uint32_t* key = g_key + (size_t)col * N_;

    s[t]        = ((uint64_t)key[t]        << 32) | (uint32_t)t;
    s[t + 1024] = ((uint64_t)key[t + 1024] << 32) | (uint32_t)(t + 1024);
    __syncthreads();

    for (int k = 2; k <= N_; k <<= 1) {
        for (int j = k >> 1; j > 0; j >>= 1) {
            int i = ((t & ~(j - 1)) << 1) | (t & (j - 1));
            int p = i | j;
            uint64_t a = s[i], b = s[p];
            bool up = ((i & k) == 0);
            if ((a > b) == up) { s[i] = b; s[p] = a; }
            __syncthreads();
        }
    }

    const int d  = col & 63;
    const int bh = col >> 6;
    float*    vs  = g_vs  + (size_t)col * N_;
    uint16_t* inv = g_inv + (size_t)col * N_;
#pragma unroll
    for (int r = t; r < N_; r += 1024) {
        uint64_t e = s[r];
        uint32_t idx = (uint32_t)e;                 // original index (0..2047)
        vs[r] = sort2f((uint32_t)(e >> 32));        // sorted value at rank r
        inv[idx] = (uint16_t)r;                     // rank of original index
        if (d == 0) g_p0[bh * N_ + r] = (uint16_t)idx;
    }
}

// ---------------- 3) out_t[bh][d][i] = vs[bh][d][ inv[bh][(d+1)%64][i] ] ----
__global__ void k_gather() {
    __shared__ float svs[N_];
    const int col = blockIdx.x;            // bh*64 + d
    const int bh = col >> 6, d = col & 63;
    const int d1 = (d + 1) & 63;
    const float*    vs   = g_vs  + (size_t)col * N_;
    const uint16_t* inv1 = g_inv + (size_t)(bh * DV_ + d1) * N_;
    float*          ot   = g_outt + (size_t)col * N_;

    for (int i = threadIdx.x; i < N_; i += blockDim.x) svs[i] = vs[i];
    __syncthreads();
    for (int i = threadIdx.x; i < N_; i += blockDim.x)
        ot[i] = svs[inv1[i]];
}

// ---------------- 4) transpose g_outt [bh][d][i] -> out [bh][i][d] ----------
__global__ void k_transpose_out(float* __restrict__ out) {
    __shared__ float tile[32][33];
    int bh = blockIdx.z;
    int i0 = blockIdx.x * 32;
    int d0 = blockIdx.y * 32;
    int tx = threadIdx.x, ty = threadIdx.y;     // block (32,8)
    const float* src = g_outt + (size_t)bh * DV_ * N_;
#pragma unroll
    for (int r = 0; r < 32; r += 8)
        tile[ty + r][tx] = src[(size_t)(d0 + ty + r) * N_ + (i0 + tx)];
    __syncthreads();
    float* dst = out + (size_t)bh * N_ * DV_;
#pragma unroll
    for (int r = 0; r < 32; r += 8)
        dst[(size_t)(i0 + ty + r) * DV_ + (d0 + tx)] = tile[tx][ty + r];
}

// ---------------- 5) attn scatter: attn[bh][i][ p0[inv1[i]] ] = 1 -----------
__global__ void k_attn(float* __restrict__ attn) {
    int gid = blockIdx.x * blockDim.x + threadIdx.x;   // bh*N + i
    int bh = gid >> 11;
    int i  = gid & (N_ - 1);
    int j    = g_inv[(size_t)(bh * DV_ + 1) * N_ + i]; // inv(p_1)[i]
    int aidx = g_p0[bh * N_ + j];                      // p_0[j]
    attn[(size_t)gid * N_ + aidx] = 1.0f;
}

// ---------------- launch -----------------------------------------------------
extern "C" void kernel_launch(void* const* d_in, const int* in_sizes, int n_in,
                              void* d_out, int out_size) {
    (void)in_sizes; (void)n_in; (void)out_size;
    const float* v = (const float*)d_in[2];      // metadata order: q, k, v
    float* out  = (float*)d_out;
    float* attn = out + OUT_ELEMS;

    // start zeroing the huge attn region first (same stream, but keeps the
    // graph simple; dominated by DRAM write bandwidth)
    cudaMemsetAsync(attn, 0, ATTN_ELEMS * sizeof(float));

    k_transpose_in <<<dim3(N_ / 32, DV_ / 32, BH_), dim3(32, 8)>>>(v);
    k_sort         <<<COLS_, 1024>>>();
    k_gather       <<<COLS_, 256>>>();
    k_transpose_out<<<dim3(N_ / 32, DV_ / 32, BH_), dim3(32, 8)>>>(out);
    k_attn         <<<(BH_ * N_) / 256, 256>>>(attn);
}